// round 9
// baseline (speedup 1.0000x reference)
#include <cuda_runtime.h>

// DRNN: two stacked SimpleRNN(tanh), persistent per-CTA kernel, round 6.
// B=512, T=512, D=64, H=100. 128 CTAs x 4 rows, 512 threads = 16 warps.
// 4 pipeline-stage groups of 4 warps (gid = wid>>2), one warp of each group
// per SMSP:
//   G_x : xp_{i+1} = W1x.x_{i+1} + b1   (feed-forward, 32 u64 wregs + x LDG)
//   G1  : h1_i    = tanh(xp_i + W1h.h1_{i-1})         (50 u64 wregs)
//   G2a : p_{i-1} = W2x.h1_{i-1} + b2                 (50 u64 wregs)
//   G2b : h2_{i-2}= tanh(p_{i-2} + W2h.h2_{i-3})      (50 u64 wregs)
// ROUND-6 CHANGE: the global per-step __syncthreads is replaced by PAIRWISE
// named barriers (bar1: Gx+G1 / bar2: G1+G2a / bar3: G2a+G2b), so the four
// groups drift instead of convoying: LDS bursts decorrelate across the SMSP
// and barrier waits involve only the actual producer/consumer. All smem
// rings are parity double-buffered; each cross-group buffer's write->read is
// ordered by exactly one shared barrier (max drift = 1 step, verified).
// fma.rn.f32x2 packs 2 MACs/instr; broadcast LDS.128; no shuffles.

#define TT   512
#define BB   512
#define DD   64
#define HH   100
#define ROWS 4
#define XSR  64     // x row stride (16 quads exact)
#define HSR  104    // h/xp/p row stride (25 quads exact + 16B-align pad)
#define NTHR 512

#define BAR_SYNC(id, cnt) asm volatile("bar.sync %0, %1;" :: "r"(id), "r"(cnt) : "memory")

__device__ __forceinline__ void ffma2(unsigned long long &acc,
                                      unsigned long long a,
                                      unsigned long long b) {
    asm("fma.rn.f32x2 %0, %1, %2, %0;" : "+l"(acc) : "l"(a), "l"(b));
}

__device__ __forceinline__ unsigned long long pack2(float lo, float hi) {
    unsigned long long r;
    asm("mov.b64 %0, {%1, %2};" : "=l"(r) : "f"(lo), "f"(hi));
    return r;
}

__device__ __forceinline__ float hsum2(unsigned long long v) {
    float lo, hi;
    asm("mov.b64 {%0, %1}, %2;" : "=f"(lo), "=f"(hi) : "l"(v));
    return lo + hi;
}

__device__ __forceinline__ ulonglong2 lds128(const float* p) {
    return *reinterpret_cast<const ulonglong2*>(p);
}

// tanh via exp + fast divide: ~1e-7 rel err, cheap tail.
__device__ __forceinline__ float tanh_f(float x) {
    float ax = fabsf(x);
    float e  = __expf(-2.0f * ax);
    float r  = __fdividef(1.0f - e, 1.0f + e);
    return copysignf(r, x);
}

// acc[r] += dot(act_row_r, w) over NQ quads; broadcast LDS (same addr/warp).
template<int NQ, int RS>
__device__ __forceinline__ void accum4(unsigned long long (&acc)[4],
                                       const float* base,
                                       const unsigned long long* w)
{
    #pragma unroll
    for (int it = 0; it < NQ; ++it) {
        ulonglong2 v0 = lds128(base + 0*RS + 4*it);
        ulonglong2 v1 = lds128(base + 1*RS + 4*it);
        ulonglong2 v2 = lds128(base + 2*RS + 4*it);
        ulonglong2 v3 = lds128(base + 3*RS + 4*it);
        unsigned long long wA = w[2*it];
        unsigned long long wB = w[2*it + 1];
        ffma2(acc[0], v0.x, wA); ffma2(acc[1], v1.x, wA);
        ffma2(acc[2], v2.x, wA); ffma2(acc[3], v3.x, wA);
        ffma2(acc[0], v0.y, wB); ffma2(acc[1], v1.y, wB);
        ffma2(acc[2], v2.y, wB); ffma2(acc[3], v3.y, wB);
    }
}

__global__ __launch_bounds__(NTHR, 1)
void drnn_kernel(const float* __restrict__ X,
                 const float* __restrict__ W1x, const float* __restrict__ W1h,
                 const float* __restrict__ B1,
                 const float* __restrict__ W2x, const float* __restrict__ W2h,
                 const float* __restrict__ B2,
                 const float* __restrict__ Wo,  const float* __restrict__ Bo,
                 float* __restrict__ out)
{
    __shared__ __align__(16) float sX [2][ROWS][XSR];
    __shared__ __align__(16) float sH1[2][ROWS][HSR];
    __shared__ __align__(16) float sH2[2][ROWS][HSR];
    __shared__ __align__(16) float sXP[2][ROWS][HSR];   // xp = W1x.x + b1
    __shared__ __align__(16) float sP [2][ROWS][HSR];   // p  = W2x.h1 + b2

    const int tid  = threadIdx.x;
    const int wid  = tid >> 5;
    const int lane = tid & 31;
    const int gid  = wid >> 2;                 // 0:Gx 1:G1 2:G2a 3:G2b
    const int wl   = wid & 3;                  // warp within group = SMSP id
    const int j    = wl * 32 + lane;           // unit 0..127
    const int jj   = (j < HH) ? j : (HH - 1);  // clamped for safe weight loads
    const bool act = (j < HH);
    const int r0   = blockIdx.x * ROWS;

    // Per-group weight column (register-resident, <=50 u64).
    unsigned long long w[50];
    #pragma unroll
    for (int n = 0; n < 50; ++n) w[n] = 0ull;
    float bj = 0.f;

    if (gid == 0) {
        #pragma unroll
        for (int q = 0; q < 16; ++q) {                 // W1x: 64 x-rows
            int k = 4 * q;
            w[2*q]   = pack2(W1x[(k  )*HH + jj], W1x[(k+1)*HH + jj]);
            w[2*q+1] = pack2(W1x[(k+2)*HH + jj], W1x[(k+3)*HH + jj]);
        }
        bj = B1[jj];                                   // b1 folded into xp
    } else {
        const float* Wsrc = (gid == 1) ? W1h : ((gid == 2) ? W2x : W2h);
        #pragma unroll
        for (int q = 0; q < 25; ++q) {                 // 100 h-rows exact
            int k = 4 * q;
            w[2*q]   = pack2(Wsrc[(k  )*HH + jj], Wsrc[(k+1)*HH + jj]);
            w[2*q+1] = pack2(Wsrc[(k+2)*HH + jj], Wsrc[(k+3)*HH + jj]);
        }
        if (gid == 2) bj = B2[jj];                     // b2 folded into p
    }

    // Zero state rings (h1_{-1} = h2_{-1} = h2_{-2}... = 0).
    {
        float* z1 = &sH1[0][0][0];
        for (int idx = tid; idx < 2*ROWS*HSR; idx += NTHR) z1[idx] = 0.f;
        float* z2 = &sH2[0][0][0];
        for (int idx = tid; idx < 2*ROWS*HSR; idx += NTHR) z2[idx] = 0.f;
    }
    // Stage x_0 -> sX[0], x_1 -> sX[1].
    {
        int p = tid & 255, buf = tid >> 8;             // 512 thr = 2 x 256
        int r = p >> 6, d = p & 63;
        sX[buf][r][d] = X[(size_t)(r0 + r)*TT*DD + (size_t)buf*DD + d];
    }
    __syncthreads();

    // Prologue: G_x computes xp_0 into sXP[0].
    if (gid == 0) {
        unsigned long long a[4] = {0ull, 0ull, 0ull, 0ull};
        accum4<16, XSR>(a, &sX[0][0][0], w);
        if (act) {
            #pragma unroll
            for (int r = 0; r < ROWS; ++r)
                sXP[0][r][j] = hsum2(a[r]) + bj;
        }
    }
    __syncthreads();

    // Steady state: pairwise named barriers only.
    //   bar 1: Gx+G1  (xp handoff, sX self-ring)
    //   bar 2: G1+G2a (h1 handoff)
    //   bar 3: G2a+G2b (p handoff, sH2 self-ring)
    for (int i = 0; i <= TT + 1; ++i) {
        const int pc = i & 1, pn = pc ^ 1;
        if (gid == 0) {
            // LDG x_{i+2} early (hidden under this step's FMA work).
            float xpfA = 0.f, xpfB = 0.f;
            const int qA = j, qB = j + 128;            // 128 lanes x 2 = 256
            const bool dl = (i + 2 < TT);
            if (dl) {
                const float* xs = X + (size_t)r0*TT*DD + (size_t)(i+2)*DD;
                xpfA = xs[(size_t)(qA >> 6)*TT*DD + (qA & 63)];
                xpfB = xs[(size_t)(qB >> 6)*TT*DD + (qB & 63)];
            }
            if (i + 1 <= TT - 1) {                     // xp_{i+1}
                unsigned long long a[4] = {0ull, 0ull, 0ull, 0ull};
                accum4<16, XSR>(a, &sX[pn][0][0], w);
                if (act) {
                    #pragma unroll
                    for (int r = 0; r < ROWS; ++r)
                        sXP[pn][r][j] = hsum2(a[r]) + bj;
                }
            }
            if (dl) {
                sX[pc][qA >> 6][qA & 63] = xpfA;
                sX[pc][qB >> 6][qB & 63] = xpfB;
            }
            BAR_SYNC(1, 256);
        } else if (gid == 1) {
            if (i <= TT - 1) {                         // h1_i
                // Hoist xp_i loads: ready since prev bar1, hidden under accum.
                float xp0 = sXP[pc][0][jj], xp1 = sXP[pc][1][jj];
                float xp2 = sXP[pc][2][jj], xp3 = sXP[pc][3][jj];
                unsigned long long a[4] = {0ull, 0ull, 0ull, 0ull};
                accum4<25, HSR>(a, &sH1[pn][0][0], w);
                if (act) {
                    sH1[pc][0][j] = tanh_f(hsum2(a[0]) + xp0);
                    sH1[pc][1][j] = tanh_f(hsum2(a[1]) + xp1);
                    sH1[pc][2][j] = tanh_f(hsum2(a[2]) + xp2);
                    sH1[pc][3][j] = tanh_f(hsum2(a[3]) + xp3);
                }
            }
            BAR_SYNC(2, 256);   // release G2a first (longer consumer chain)
            BAR_SYNC(1, 256);
        } else if (gid == 2) {
            if (i >= 1 && i <= TT) {                   // p_{i-1}
                unsigned long long a[4] = {0ull, 0ull, 0ull, 0ull};
                accum4<25, HSR>(a, &sH1[pn][0][0], w);
                if (act) {
                    #pragma unroll
                    for (int r = 0; r < ROWS; ++r)
                        sP[pn][r][j] = hsum2(a[r]) + bj;
                }
            }
            BAR_SYNC(3, 256);   // release G2b first
            BAR_SYNC(2, 256);
        } else {
            if (i >= 2) {                              // h2_{i-2}
                float p0 = sP[pc][0][jj], p1 = sP[pc][1][jj];
                float p2 = sP[pc][2][jj], p3 = sP[pc][3][jj];
                unsigned long long a[4] = {0ull, 0ull, 0ull, 0ull};
                accum4<25, HSR>(a, &sH2[pn][0][0], w);
                if (act) {
                    sH2[pc][0][j] = tanh_f(hsum2(a[0]) + p0);
                    sH2[pc][1][j] = tanh_f(hsum2(a[1]) + p1);
                    sH2[pc][2][j] = tanh_f(hsum2(a[2]) + p2);
                    sH2[pc][3][j] = tanh_f(hsum2(a[3]) + p3);
                }
            }
            BAR_SYNC(3, 256);
        }
    }
    __syncthreads();

    // h1_511 in sH1[1], h2_511 in sH2[1] (written at wall-step 513, pc=1).
    float* outVec = out;                      // [512]
    float* outH1  = out + BB;                 // [512,100]
    float* outH2  = out + BB + BB*HH;         // [512,100]

    for (int idx = tid; idx < ROWS*HH; idx += NTHR) {
        int r = idx / HH, u = idx % HH;
        outH1[(size_t)(r0 + r)*HH + u] = sH1[1][r][u];
        outH2[(size_t)(r0 + r)*HH + u] = sH2[1][r][u];
    }

    // Output head: out[r] = h2_T[r] . Wo + bo  (warp 0).
    if (tid < 32) {
        #pragma unroll
        for (int r = 0; r < ROWS; ++r) {
            float v = 0.f;
            #pragma unroll
            for (int mm = 0; mm < 4; ++mm) {
                int u = mm*32 + tid;
                if (u < HH) v += sH2[1][r][u] * Wo[u];
            }
            #pragma unroll
            for (int off = 16; off; off >>= 1)
                v += __shfl_down_sync(0xffffffffu, v, off);
            if (tid == 0) outVec[r0 + r] = v + Bo[0];
        }
    }
}

extern "C" void kernel_launch(void* const* d_in, const int* in_sizes, int n_in,
                              void* d_out, int out_size) {
    (void)in_sizes; (void)n_in; (void)out_size;
    const float* X   = (const float*)d_in[0];
    const float* W1x = (const float*)d_in[1];
    const float* W1h = (const float*)d_in[2];
    const float* B1  = (const float*)d_in[3];
    const float* W2x = (const float*)d_in[4];
    const float* W2h = (const float*)d_in[5];
    const float* B2  = (const float*)d_in[6];
    const float* Wo  = (const float*)d_in[7];
    const float* Bo  = (const float*)d_in[8];
    drnn_kernel<<<BB/ROWS, NTHR>>>(X, W1x, W1h, B1, W2x, W2h, B2, Wo, Bo,
                                   (float*)d_out);
}

// round 10
// speedup vs baseline: 1.3114x; 1.3114x over previous
#include <cuda_runtime.h>

// DRNN: two stacked SimpleRNN(tanh), persistent per-CTA kernel, round 7.
// B=512, T=512, D=64, H=100. 128 CTAs x 4 rows, 256 threads = 8 warps.
// Finding (R0/R7/R8): runtime is pinned by SM-wide broadcast-LDS.128
// throughput (~2.3 cyc/instr, ~1456 instr/step in all prior variants).
// ROUND-7 CHANGE: each lane owns TWO adjacent units with FULL k-columns
// (no k-split, no shuffles), so each stage needs only 2 warps and every
// activation LDS.128 feeds 16 FFMA2 -> 728 LDS.128/step (halved).
// 4 pipeline-stage groups of 2 warps (gid = wid>>1):
//   G_x (wid 0,1): xp_{i+1} = W1x.x_{i+1} + b1   (64 u64 wregs + x LDG)
//   G1  (wid 2,3): h1_i    = tanh(xp_i + W1h.h1_{i-1})   (100 u64 wregs)
//   G2a (wid 4,5): p_{i-1} = W2x.h1_{i-1} + b2           (100 u64 wregs)
//   G2b (wid 6,7): h2_{i-2}= tanh(p_{i-2} + W2h.h2_{i-3})(100 u64 wregs)
// Pairwise named barriers (bar1: Gx+G1, bar2: G1+G2a, bar3: G2a+G2b),
// parity double-buffered smem rings, fma.rn.f32x2 (2 MACs/instr).

#define TT   512
#define BB   512
#define DD   64
#define HH   100
#define ROWS 4
#define XSR  64     // x row stride (16 quads exact)
#define HSR  104    // h/xp/p row stride (25 quads exact + 16B-align pad)
#define NTHR 256

#define BAR_SYNC(id, cnt) asm volatile("bar.sync %0, %1;" :: "r"(id), "r"(cnt) : "memory")

__device__ __forceinline__ void ffma2(unsigned long long &acc,
                                      unsigned long long a,
                                      unsigned long long b) {
    asm("fma.rn.f32x2 %0, %1, %2, %0;" : "+l"(acc) : "l"(a), "l"(b));
}

__device__ __forceinline__ unsigned long long pack2(float lo, float hi) {
    unsigned long long r;
    asm("mov.b64 %0, {%1, %2};" : "=l"(r) : "f"(lo), "f"(hi));
    return r;
}

__device__ __forceinline__ float hsum2(unsigned long long v) {
    float lo, hi;
    asm("mov.b64 {%0, %1}, %2;" : "=f"(lo), "=f"(hi) : "l"(v));
    return lo + hi;
}

__device__ __forceinline__ ulonglong2 lds128(const float* p) {
    return *reinterpret_cast<const ulonglong2*>(p);
}

// tanh via exp + fast divide: ~1e-7 rel err.
__device__ __forceinline__ float tanh_f(float x) {
    float ax = fabsf(x);
    float e  = __expf(-2.0f * ax);
    float r  = __fdividef(1.0f - e, 1.0f + e);
    return copysignf(r, x);
}

// Dual-unit accumulate: acc[r] (unit0), acc[4+r] (unit1), r = row 0..3.
// Per iter: 4 broadcast LDS.128 feed 16 FFMA2.
// Weight layout: w[4*it + {0,1,2,3}] = {u0_loA, u0_hiB, u1_loA, u1_hiB}.
template<int NQ, int RS>
__device__ __forceinline__ void accum8(unsigned long long (&acc)[8],
                                       const float* base,
                                       const unsigned long long* w)
{
    #pragma unroll
    for (int it = 0; it < NQ; ++it) {
        ulonglong2 v0 = lds128(base + 0*RS + 4*it);
        ulonglong2 v1 = lds128(base + 1*RS + 4*it);
        ulonglong2 v2 = lds128(base + 2*RS + 4*it);
        ulonglong2 v3 = lds128(base + 3*RS + 4*it);
        unsigned long long wA0 = w[4*it + 0];
        unsigned long long wB0 = w[4*it + 1];
        unsigned long long wA1 = w[4*it + 2];
        unsigned long long wB1 = w[4*it + 3];
        ffma2(acc[0], v0.x, wA0); ffma2(acc[4], v0.x, wA1);
        ffma2(acc[1], v1.x, wA0); ffma2(acc[5], v1.x, wA1);
        ffma2(acc[2], v2.x, wA0); ffma2(acc[6], v2.x, wA1);
        ffma2(acc[3], v3.x, wA0); ffma2(acc[7], v3.x, wA1);
        ffma2(acc[0], v0.y, wB0); ffma2(acc[4], v0.y, wB1);
        ffma2(acc[1], v1.y, wB0); ffma2(acc[5], v1.y, wB1);
        ffma2(acc[2], v2.y, wB0); ffma2(acc[6], v2.y, wB1);
        ffma2(acc[3], v3.y, wB0); ffma2(acc[7], v3.y, wB1);
    }
}

__global__ __launch_bounds__(NTHR, 1)
void drnn_kernel(const float* __restrict__ X,
                 const float* __restrict__ W1x, const float* __restrict__ W1h,
                 const float* __restrict__ B1,
                 const float* __restrict__ W2x, const float* __restrict__ W2h,
                 const float* __restrict__ B2,
                 const float* __restrict__ Wo,  const float* __restrict__ Bo,
                 float* __restrict__ out)
{
    __shared__ __align__(16) float sX [2][ROWS][XSR];
    __shared__ __align__(16) float sH1[2][ROWS][HSR];
    __shared__ __align__(16) float sH2[2][ROWS][HSR];
    __shared__ __align__(16) float sXP[2][ROWS][HSR];   // xp = W1x.x + b1
    __shared__ __align__(16) float sP [2][ROWS][HSR];   // p  = W2x.h1 + b2

    const int tid  = threadIdx.x;
    const int wid  = tid >> 5;
    const int lane = tid & 31;
    const int gid  = wid >> 1;                 // 0:Gx 1:G1 2:G2a 3:G2b
    const int wl   = wid & 1;                  // warp within group
    const int j0   = wl * 32 + lane;           // 0..63
    const bool act = (j0 < 50);
    const int jc   = act ? j0 : 49;            // clamped
    const int u0   = 2 * jc;                   // units u0, u0+1
    const int r0   = blockIdx.x * ROWS;

    // Per-thread weights: two full columns of one matrix.
    // Gx uses w[0..63] (16 iters), others w[0..99] (25 iters).
    unsigned long long w[100];
    #pragma unroll
    for (int n = 0; n < 100; ++n) w[n] = 0ull;
    float bj0 = 0.f, bj1 = 0.f;

    if (gid == 0) {
        #pragma unroll
        for (int q = 0; q < 16; ++q) {
            int k = 4 * q;
            w[4*q+0] = pack2(W1x[(k  )*HH + u0], W1x[(k+1)*HH + u0]);
            w[4*q+1] = pack2(W1x[(k+2)*HH + u0], W1x[(k+3)*HH + u0]);
            w[4*q+2] = pack2(W1x[(k  )*HH + u0+1], W1x[(k+1)*HH + u0+1]);
            w[4*q+3] = pack2(W1x[(k+2)*HH + u0+1], W1x[(k+3)*HH + u0+1]);
        }
        bj0 = B1[u0]; bj1 = B1[u0+1];          // b1 folded into xp
    } else {
        const float* Wsrc = (gid == 1) ? W1h : ((gid == 2) ? W2x : W2h);
        #pragma unroll
        for (int q = 0; q < 25; ++q) {
            int k = 4 * q;
            w[4*q+0] = pack2(Wsrc[(k  )*HH + u0], Wsrc[(k+1)*HH + u0]);
            w[4*q+1] = pack2(Wsrc[(k+2)*HH + u0], Wsrc[(k+3)*HH + u0]);
            w[4*q+2] = pack2(Wsrc[(k  )*HH + u0+1], Wsrc[(k+1)*HH + u0+1]);
            w[4*q+3] = pack2(Wsrc[(k+2)*HH + u0+1], Wsrc[(k+3)*HH + u0+1]);
        }
        if (gid == 2) { bj0 = B2[u0]; bj1 = B2[u0+1]; }  // b2 folded into p
    }

    // Zero state rings (h1_{-1} = h2_{-1} = ... = 0; pads finite-0).
    {
        float* z1 = &sH1[0][0][0];
        for (int idx = tid; idx < 2*ROWS*HSR; idx += NTHR) z1[idx] = 0.f;
        float* z2 = &sH2[0][0][0];
        for (int idx = tid; idx < 2*ROWS*HSR; idx += NTHR) z2[idx] = 0.f;
    }
    // Stage x_0 -> sX[0], x_1 -> sX[1] (256 thr x 2 values).
    #pragma unroll
    for (int s = 0; s < 2; ++s) {
        int n = tid + s * NTHR;                // 0..511
        int buf = n >> 8, r = (n >> 6) & 3, d = n & 63;
        sX[buf][r][d] = X[(size_t)(r0 + r)*TT*DD + (size_t)buf*DD + d];
    }
    __syncthreads();

    // Prologue: G_x computes xp_0 into sXP[0].
    if (gid == 0) {
        unsigned long long a[8];
        #pragma unroll
        for (int n = 0; n < 8; ++n) a[n] = 0ull;
        accum8<16, XSR>(a, &sX[0][0][0], w);
        if (act) {
            #pragma unroll
            for (int r = 0; r < ROWS; ++r) {
                float2 v; v.x = hsum2(a[r]) + bj0; v.y = hsum2(a[4+r]) + bj1;
                *reinterpret_cast<float2*>(&sXP[0][r][u0]) = v;
            }
        }
    }
    __syncthreads();

    // Steady state: pairwise named barriers.
    //   bar 1: Gx+G1 (xp handoff, sX self-ring)     [128 thr]
    //   bar 2: G1+G2a (h1 handoff)                   [128 thr]
    //   bar 3: G2a+G2b (p handoff, sH2 self-ring)    [128 thr]
    for (int i = 0; i <= TT + 1; ++i) {
        const int pc = i & 1, pn = pc ^ 1;
        if (gid == 0) {
            // LDG x_{i+2} early (hidden under FMA work). 64 lanes x 4 = 256.
            float xpf[4];
            const bool dl = (i + 2 < TT);
            if (dl) {
                const float* xs = X + (size_t)r0*TT*DD + (size_t)(i+2)*DD;
                #pragma unroll
                for (int s = 0; s < 4; ++s) {
                    int n = j0 + 64 * s;
                    xpf[s] = xs[(size_t)(n >> 6)*TT*DD + (n & 63)];
                }
            }
            if (i + 1 <= TT - 1) {                     // xp_{i+1}
                unsigned long long a[8];
                #pragma unroll
                for (int n = 0; n < 8; ++n) a[n] = 0ull;
                accum8<16, XSR>(a, &sX[pn][0][0], w);
                if (act) {
                    #pragma unroll
                    for (int r = 0; r < ROWS; ++r) {
                        float2 v; v.x = hsum2(a[r]) + bj0; v.y = hsum2(a[4+r]) + bj1;
                        *reinterpret_cast<float2*>(&sXP[pn][r][u0]) = v;
                    }
                }
            }
            if (dl) {
                #pragma unroll
                for (int s = 0; s < 4; ++s) {
                    int n = j0 + 64 * s;
                    sX[pc][n >> 6][n & 63] = xpf[s];
                }
            }
            BAR_SYNC(1, 128);
        } else if (gid == 1) {
            if (i <= TT - 1) {                         // h1_i
                // Hoist xp_i (ready since prev bar1; hidden under accum).
                float2 xp[4];
                #pragma unroll
                for (int r = 0; r < ROWS; ++r)
                    xp[r] = *reinterpret_cast<const float2*>(&sXP[pc][r][u0]);
                unsigned long long a[8];
                #pragma unroll
                for (int n = 0; n < 8; ++n) a[n] = 0ull;
                accum8<25, HSR>(a, &sH1[pn][0][0], w);
                if (act) {
                    #pragma unroll
                    for (int r = 0; r < ROWS; ++r) {
                        float2 v;
                        v.x = tanh_f(hsum2(a[r])   + xp[r].x);
                        v.y = tanh_f(hsum2(a[4+r]) + xp[r].y);
                        *reinterpret_cast<float2*>(&sH1[pc][r][u0]) = v;
                    }
                }
            }
            BAR_SYNC(2, 128);   // release G2a first (longer consumer chain)
            BAR_SYNC(1, 128);
        } else if (gid == 2) {
            if (i >= 1 && i <= TT) {                   // p_{i-1}
                unsigned long long a[8];
                #pragma unroll
                for (int n = 0; n < 8; ++n) a[n] = 0ull;
                accum8<25, HSR>(a, &sH1[pn][0][0], w);
                if (act) {
                    #pragma unroll
                    for (int r = 0; r < ROWS; ++r) {
                        float2 v; v.x = hsum2(a[r]) + bj0; v.y = hsum2(a[4+r]) + bj1;
                        *reinterpret_cast<float2*>(&sP[pn][r][u0]) = v;
                    }
                }
            }
            BAR_SYNC(3, 128);   // release G2b first
            BAR_SYNC(2, 128);
        } else {
            if (i >= 2) {                              // h2_{i-2}
                float2 pv[4];
                #pragma unroll
                for (int r = 0; r < ROWS; ++r)
                    pv[r] = *reinterpret_cast<const float2*>(&sP[pc][r][u0]);
                unsigned long long a[8];
                #pragma unroll
                for (int n = 0; n < 8; ++n) a[n] = 0ull;
                accum8<25, HSR>(a, &sH2[pn][0][0], w);
                if (act) {
                    #pragma unroll
                    for (int r = 0; r < ROWS; ++r) {
                        float2 v;
                        v.x = tanh_f(hsum2(a[r])   + pv[r].x);
                        v.y = tanh_f(hsum2(a[4+r]) + pv[r].y);
                        *reinterpret_cast<float2*>(&sH2[pc][r][u0]) = v;
                    }
                }
            }
            BAR_SYNC(3, 128);
        }
    }
    __syncthreads();

    // h1_511 in sH1[1], h2_511 in sH2[1].
    float* outVec = out;                      // [512]
    float* outH1  = out + BB;                 // [512,100]
    float* outH2  = out + BB + BB*HH;         // [512,100]

    for (int idx = tid; idx < ROWS*HH; idx += NTHR) {
        int r = idx / HH, u = idx % HH;
        outH1[(size_t)(r0 + r)*HH + u] = sH1[1][r][u];
        outH2[(size_t)(r0 + r)*HH + u] = sH2[1][r][u];
    }

    // Output head: out[r] = h2_T[r] . Wo + bo  (warp 0).
    if (tid < 32) {
        #pragma unroll
        for (int r = 0; r < ROWS; ++r) {
            float v = 0.f;
            #pragma unroll
            for (int mm = 0; mm < 4; ++mm) {
                int u = mm*32 + tid;
                if (u < HH) v += sH2[1][r][u] * Wo[u];
            }
            #pragma unroll
            for (int off = 16; off; off >>= 1)
                v += __shfl_down_sync(0xffffffffu, v, off);
            if (tid == 0) outVec[r0 + r] = v + Bo[0];
        }
    }
}

extern "C" void kernel_launch(void* const* d_in, const int* in_sizes, int n_in,
                              void* d_out, int out_size) {
    (void)in_sizes; (void)n_in; (void)out_size;
    const float* X   = (const float*)d_in[0];
    const float* W1x = (const float*)d_in[1];
    const float* W1h = (const float*)d_in[2];
    const float* B1  = (const float*)d_in[3];
    const float* W2x = (const float*)d_in[4];
    const float* W2h = (const float*)d_in[5];
    const float* B2  = (const float*)d_in[6];
    const float* Wo  = (const float*)d_in[7];
    const float* Bo  = (const float*)d_in[8];
    drnn_kernel<<<BB/ROWS, NTHR>>>(X, W1x, W1h, B1, W2x, W2h, B2, Wo, Bo,
                                   (float*)d_out);
}